// round 16
// baseline (speedup 1.0000x reference)
#include <cuda_runtime.h>
#include <cuda_bf16.h>
#include <cuda_fp8.h>
#include <math.h>
#include <stdint.h>

// Problem-instance maxima (N=10000, M=50000, fixed shapes per reference)
#define NMAX 10016
#define D_IN 32
#define DOUT 64
#define EMB 256
#define EPS 1e-5f
// log2(e)/TEMP,  TEMP = 0.2
#define SIM_SCALE 7.2134752044448170f

// ---------------- scratch (static device globals; no allocation) -------------
__device__ float g_prod[3 * NMAX * D_IN];             // normalized riemannian feats
__device__ uint8_t g_xa[NMAX * EMB];                  // row-normalized x   (fp8 e4m3)
__device__ uint8_t g_xb[NMAX * EMB];                  // row-normalized x2  (fp8 e4m3)
__device__ float g_H[4 * NMAX * 192];                 // MLP layer-1 partials
__device__ float g_rowsum[NMAX];
__device__ float g_colsum[NMAX];
__device__ float g_diag[NMAX];
__device__ double g_macc;                             // motif log-sigmoid sum
__device__ double g_clacc;                            // contrastive log-ratio sum

__device__ __forceinline__ uint32_t smem_u32(const void* p) {
    uint32_t a;
    asm("{ .reg .u64 t; cvta.to.shared.u64 t, %1; cvt.u32.u64 %0, t; }" : "=r"(a) : "l"(p));
    return a;
}
__device__ __forceinline__ void cp_async16(uint32_t dst, const void* src, bool pred) {
    int sz = pred ? 16 : 0;
    asm volatile("cp.async.cg.shared.global [%0], [%1], 16, %2;"
                 :: "r"(dst), "l"(src), "r"(sz) : "memory");
}
#define CP_COMMIT() asm volatile("cp.async.commit_group;" ::: "memory")
#define CP_WAIT(n)  asm volatile("cp.async.wait_group %0;" :: "n"(n) : "memory")

__device__ __forceinline__ uint32_t to_fp8(float v) {
    __nv_fp8_e4m3 f(v);
    return (uint32_t)*reinterpret_cast<uint8_t*>(&f);
}

// ---------------- 1: normalize feats AND x (merged, + zero accumulators) ------
__global__ void norm_all_kernel(const float* __restrict__ feats,
                                const float* __restrict__ ks,
                                const float* __restrict__ x, int N) {
    int tid = blockIdx.x * blockDim.x + threadIdx.x;
    if (tid < N) { g_rowsum[tid] = 0.f; g_colsum[tid] = 0.f; }
    if (tid == 0) { g_macc = 0.0; g_clacc = 0.0; }
    int gw = tid >> 5;
    int lane = tid & 31;
    if (gw < 3 * N) {
        float v = feats[(size_t)gw * D_IN + lane];
        float sq = v * v;
        #pragma unroll
        for (int off = 16; off; off >>= 1) sq += __shfl_xor_sync(0xffffffffu, sq, off);
        float k = ks[gw / N];
        float scale = 0.45f / (sqrtf(sq) * sqrtf(fabsf(k)));
        g_prod[(size_t)gw * D_IN + lane] = v * scale;
    } else if (gw < 4 * N) {
        int row = gw - 3 * N;
        const float4* rp = (const float4*)(x + (size_t)row * EMB);
        float4 v0 = rp[lane * 2];
        float4 v1 = rp[lane * 2 + 1];
        float sq = v0.x * v0.x + v0.y * v0.y + v0.z * v0.z + v0.w * v0.w
                 + v1.x * v1.x + v1.y * v1.y + v1.z * v1.z + v1.w * v1.w;
        #pragma unroll
        for (int off = 16; off; off >>= 1) sq += __shfl_xor_sync(0xffffffffu, sq, off);
        float inv = rsqrtf(sq);
        uint2 o;
        o.x = to_fp8(v0.x * inv) | (to_fp8(v0.y * inv) << 8)
            | (to_fp8(v0.z * inv) << 16) | (to_fp8(v0.w * inv) << 24);
        o.y = to_fp8(v1.x * inv) | (to_fp8(v1.y * inv) << 8)
            | (to_fp8(v1.z * inv) << 16) | (to_fp8(v1.w * inv) << 24);
        *(uint2*)(g_xa + (size_t)row * EMB + lane * 8) = o;
    }
}

// ---------------- 2: build x2 (random mapping), normalize, -> fp8 -------------
#define X2_ROWS 8
__global__ __launch_bounds__(256) void build_x2_kernel(
        const float* __restrict__ feat_free,
        const float* __restrict__ ks,
        const float* __restrict__ Ws,
        const float* __restrict__ bias,
        const float* __restrict__ W_free,
        const float* __restrict__ b_free,
        int N) {
    __shared__ float ws[3 * 32 * 65];     // [f][c][col], c-stride 65
    __shared__ float wf[32 * 65];         // [c][col]
    __shared__ __align__(16) float xi[X2_ROWS][128];
    __shared__ float red[X2_ROWS][256];
    const int n0 = blockIdx.x * X2_ROWS;
    const int t = threadIdx.x;

    #pragma unroll
    for (int k = 0; k < 6; k++) {
        int idx4 = t + k * 256;
        float4 v = ((const float4*)Ws)[idx4];
        int row = idx4 >> 3;
        int c0 = (idx4 & 7) * 4;
        int f = row >> 6, col = row & 63;
        float* dst = ws + f * (32 * 65) + col;
        dst[(c0 + 0) * 65] = v.x; dst[(c0 + 1) * 65] = v.y;
        dst[(c0 + 2) * 65] = v.z; dst[(c0 + 3) * 65] = v.w;
    }
    #pragma unroll
    for (int k = 0; k < 2; k++) {
        int idx4 = t + k * 256;
        float4 v = ((const float4*)W_free)[idx4];
        int col = idx4 >> 3;
        int c0 = (idx4 & 7) * 4;
        float* dst = wf + col;
        dst[(c0 + 0) * 65] = v.x; dst[(c0 + 1) * 65] = v.y;
        dst[(c0 + 2) * 65] = v.z; dst[(c0 + 3) * 65] = v.w;
    }
    #pragma unroll
    for (int rr = 0; rr < 4; rr++) {
        int idx = t + rr * 256;
        int r = idx >> 7;
        int c = idx & 127;
        int n = n0 + r;
        float v;
        if (n < N) {
            v = (c < 96) ? g_prod[((c >> 5) * N + n) * D_IN + (c & 31)]
                         : feat_free[n * D_IN + (c - 96)];
        } else v = 1.f;
        xi[r][c] = v;
    }
    __syncthreads();

    const int f = t >> 6;
    const int col = t & 63;
    const float kf = (f < 3) ? ks[f] : 0.f;
    const float bv = (f < 3) ? bias[f * DOUT + col] : b_free[col];

    float z[X2_ROWS];
    #pragma unroll
    for (int r = 0; r < X2_ROWS; r++) {
        float zv;
        if (f < 3) {
            const float4* xv4 = (const float4*)(xi[r] + f * D_IN);   // broadcast LDS.128
            const float* wv = ws + f * (32 * 65) + col;
            float nsq = 0.f, dot = 0.f;
            #pragma unroll
            for (int cq = 0; cq < 8; cq++) {
                float4 xv = xv4[cq];
                nsq += xv.x * xv.x; dot += xv.x * wv[(cq * 4 + 0) * 65];
                nsq += xv.y * xv.y; dot += xv.y * wv[(cq * 4 + 1) * 65];
                nsq += xv.z * xv.z; dot += xv.z * wv[(cq * 4 + 2) * 65];
                nsq += xv.w * xv.w; dot += xv.w * wv[(cq * 4 + 3) * 65];
            }
            float div = nsq - 2.f * dot + 1.f;
            float num = 1.f + kf * nsq;
            float dist = logf(num / (div + EPS));
            zv = expf(15.5f * dist) * cosf(dist + bv);
        } else {
            const float4* xv4 = (const float4*)(xi[r] + 3 * D_IN);
            const float* wv = wf + col;
            float dot = 0.f;
            #pragma unroll
            for (int cq = 0; cq < 8; cq++) {
                float4 xv = xv4[cq];
                dot += xv.x * wv[(cq * 4 + 0) * 65];
                dot += xv.y * wv[(cq * 4 + 1) * 65];
                dot += xv.z * wv[(cq * 4 + 2) * 65];
                dot += xv.w * wv[(cq * 4 + 3) * 65];
            }
            zv = expf(15.5f * dot) * cosf(dot + bv);
        }
        z[r] = zv;
        red[r][t] = zv * zv;
    }
    __syncthreads();
    #pragma unroll
    for (int s = 128; s > 0; s >>= 1) {
        if (t < s) {
            #pragma unroll
            for (int r = 0; r < X2_ROWS; r++) red[r][t] += red[r][t + s];
        }
        __syncthreads();
    }
    #pragma unroll
    for (int r = 0; r < X2_ROWS; r++) {
        int n = n0 + r;
        if (n < N) {
            float inv = rsqrtf(red[r][0]);
            g_xb[(size_t)n * EMB + t] = (uint8_t)to_fp8(z[r] * inv);
        }
    }
}

// ---------------- 3: H = product_p @ W1 (2 rows x 4 cols per thread) ----------
#define BH_ROWS 32
__global__ __launch_bounds__(256) void build_H_kernel(
        const float* __restrict__ feat_free,
        const float* __restrict__ W1, int N) {
    __shared__ float w1s[96 * 64];        // 24 KB
    __shared__ float rows[BH_ROWS][33];   // 4.2 KB, padded
    const int t = threadIdx.x;
    const int q0 = blockIdx.x * BH_ROWS;

    #pragma unroll
    for (int k = 0; k < 6; k++) {
        int i4 = t + k * 256;
        ((float4*)w1s)[i4] = ((const float4*)W1)[i4];
    }
    #pragma unroll
    for (int k = 0; k < 4; k++) {
        int idx = t + k * 256;
        int r = idx >> 5, c = idx & 31;
        int q = q0 + r;
        float v = 0.f;
        if (q < 4 * N) {
            int p = q / N, n = q % N;
            v = (p < 3) ? g_prod[((size_t)p * N + n) * D_IN + c]
                        : feat_free[(size_t)n * D_IN + c];
        }
        rows[r][c] = v;
    }
    __syncthreads();

    const int jj = (t & 15) * 4;          // 16 col groups
    const int r0 = (t >> 4) * 2;          // 16 row groups x 2 rows
    #pragma unroll
    for (int part = 0; part < 3; part++) {
        float4 a0 = make_float4(0.f, 0.f, 0.f, 0.f);
        float4 a1 = make_float4(0.f, 0.f, 0.f, 0.f);
        #pragma unroll
        for (int c = 0; c < 32; c++) {
            float4 w = *(const float4*)&w1s[(part * 32 + c) * 64 + jj];
            float r0v = rows[r0][c];
            float r1v = rows[r0 + 1][c];
            a0.x += r0v * w.x; a0.y += r0v * w.y; a0.z += r0v * w.z; a0.w += r0v * w.w;
            a1.x += r1v * w.x; a1.y += r1v * w.y; a1.z += r1v * w.z; a1.w += r1v * w.w;
        }
        int q = q0 + r0;
        if (q < 4 * N)
            *(float4*)(g_H + (size_t)q * 192 + part * 64 + jj) = a0;
        if (q + 1 < 4 * N)
            *(float4*)(g_H + (size_t)(q + 1) * 192 + part * 64 + jj) = a1;
    }
}

// ---------------- 4: sim GEMM: fp8 e4m3 mma.sync m16n8k32 ----------------------
#define TILE 128
#define BKB 128               // bytes of K per stage (= 128 fp8 elems)
#define RSB 144               // smem row stride in bytes (128 data + 16 pad)
#define MAT_BYTES (TILE * RSB)             // 18432
#define STAGE_BYTES (2 * MAT_BYTES)        // 36864
#define SIM_SMEM (2 * STAGE_BYTES)         // 73728

__global__ __launch_bounds__(256, 2) void sim_hmma_kernel(int N) {
    extern __shared__ char dynsm[];
    __shared__ float sRow[TILE];
    __shared__ float sCol[TILE];

    const uint32_t sbase = smem_u32(dynsm);
    const int t = threadIdx.x;
    const int lane = t & 31;
    const int wid = t >> 5;
    const int warp_m = wid & 1;
    const int warp_n = wid >> 1;
    const int g = lane >> 2;
    const int tig = lane & 3;
    const int i0 = blockIdx.y * TILE;
    const int j0 = blockIdx.x * TILE;

    const uint8_t* GA = g_xa;
    const uint8_t* GB = g_xb;

    if (t < TILE) { sRow[t] = 0.f; sCol[t] = 0.f; }

    {
        #pragma unroll
        for (int it = 0; it < 4; it++) {
            int id = t + it * 256;
            int row = id >> 3, ch = id & 7;
            cp_async16(sbase + row * RSB + ch * 16,
                       GA + (size_t)(i0 + row) * EMB + ch * 16, i0 + row < N);
        }
        #pragma unroll
        for (int it = 0; it < 4; it++) {
            int id = t + it * 256;
            int row = id >> 3, ch = id & 7;
            cp_async16(sbase + MAT_BYTES + row * RSB + ch * 16,
                       GB + (size_t)(j0 + row) * EMB + ch * 16, j0 + row < N);
        }
        CP_COMMIT();
    }

    float acc[4][4][4];
    #pragma unroll
    for (int mt = 0; mt < 4; mt++)
        #pragma unroll
        for (int nt = 0; nt < 4; nt++)
            #pragma unroll
            for (int c = 0; c < 4; c++) acc[mt][nt][c] = 0.f;

    const int aRow = lane & 15;
    const int aColB = (lane >> 4) * 16;
    const int bRow = (lane & 7) + ((lane >> 4) << 3);
    const int bColB = ((lane >> 3) & 1) * 16;

    #pragma unroll
    for (int s = 0; s < EMB / BKB; s++) {
        CP_WAIT(0);
        __syncthreads();

        if (s + 1 < EMB / BKB) {
            uint32_t dst = sbase + ((s + 1) & 1) * STAGE_BYTES;
            const int koff = (s + 1) * BKB;
            #pragma unroll
            for (int it = 0; it < 4; it++) {
                int id = t + it * 256;
                int row = id >> 3, ch = id & 7;
                cp_async16(dst + row * RSB + ch * 16,
                           GA + (size_t)(i0 + row) * EMB + koff + ch * 16, i0 + row < N);
            }
            #pragma unroll
            for (int it = 0; it < 4; it++) {
                int id = t + it * 256;
                int row = id >> 3, ch = id & 7;
                cp_async16(dst + MAT_BYTES + row * RSB + ch * 16,
                           GB + (size_t)(j0 + row) * EMB + koff + ch * 16, j0 + row < N);
            }
            CP_COMMIT();
        }

        const uint32_t aB = sbase + (s & 1) * STAGE_BYTES;
        const uint32_t bB = aB + MAT_BYTES;

        #pragma unroll
        for (int kk = 0; kk < BKB / 32; kk++) {
            const int k0b = kk * 32;
            uint32_t a[4][4];
            #pragma unroll
            for (int mt = 0; mt < 4; mt++) {
                uint32_t addr = aB + (warp_m * 64 + mt * 16 + aRow) * RSB + k0b + aColB;
                asm volatile("ldmatrix.sync.aligned.m8n8.x4.shared.b16 {%0,%1,%2,%3}, [%4];"
                             : "=r"(a[mt][0]), "=r"(a[mt][1]), "=r"(a[mt][2]), "=r"(a[mt][3])
                             : "r"(addr));
            }
            uint32_t b[4][2];
            #pragma unroll
            for (int bq = 0; bq < 2; bq++) {
                uint32_t addr = bB + (warp_n * 32 + bq * 16 + bRow) * RSB + k0b + bColB;
                uint32_t r0, r1, r2, r3;
                asm volatile("ldmatrix.sync.aligned.m8n8.x4.shared.b16 {%0,%1,%2,%3}, [%4];"
                             : "=r"(r0), "=r"(r1), "=r"(r2), "=r"(r3)
                             : "r"(addr));
                b[bq * 2][0] = r0;     b[bq * 2][1] = r1;
                b[bq * 2 + 1][0] = r2; b[bq * 2 + 1][1] = r3;
            }
            #pragma unroll
            for (int mt = 0; mt < 4; mt++)
                #pragma unroll
                for (int nt = 0; nt < 4; nt++) {
                    asm volatile(
                        "mma.sync.aligned.m16n8k32.row.col.f32.e4m3.e4m3.f32 "
                        "{%0,%1,%2,%3}, {%4,%5,%6,%7}, {%8,%9}, {%0,%1,%2,%3};"
                        : "+f"(acc[mt][nt][0]), "+f"(acc[mt][nt][1]),
                          "+f"(acc[mt][nt][2]), "+f"(acc[mt][nt][3])
                        : "r"(a[mt][0]), "r"(a[mt][1]), "r"(a[mt][2]), "r"(a[mt][3]),
                          "r"(b[nt][0]), "r"(b[nt][1]));
                }
        }
    }

    const bool full = (i0 + TILE <= N) && (j0 + TILE <= N);
    const bool isdiag = (i0 == j0);

    float rp[8];
    float cp[8];
    #pragma unroll
    for (int r = 0; r < 8; r++) { rp[r] = 0.f; cp[r] = 0.f; }

    if (full) {
        #pragma unroll
        for (int mt = 0; mt < 4; mt++) {
            #pragma unroll
            for (int nt = 0; nt < 4; nt++) {
                float e0 = exp2f(acc[mt][nt][0] * SIM_SCALE);
                float e1 = exp2f(acc[mt][nt][1] * SIM_SCALE);
                float e2 = exp2f(acc[mt][nt][2] * SIM_SCALE);
                float e3 = exp2f(acc[mt][nt][3] * SIM_SCALE);
                rp[mt * 2]     += e0 + e1;
                rp[mt * 2 + 1] += e2 + e3;
                cp[nt * 2]     += e0 + e2;
                cp[nt * 2 + 1] += e1 + e3;
            }
        }
        if (isdiag) {
            #pragma unroll
            for (int mt = 0; mt < 4; mt++) {
                int i_lo = i0 + warp_m * 64 + mt * 16 + g;
                int i_hi = i_lo + 8;
                #pragma unroll
                for (int nt = 0; nt < 4; nt++) {
                    int j_e = j0 + warp_n * 32 + nt * 8 + 2 * tig;
                    int j_o = j_e + 1;
                    if (i_lo == j_e) g_diag[i_lo] = exp2f(acc[mt][nt][0] * SIM_SCALE);
                    if (i_lo == j_o) g_diag[i_lo] = exp2f(acc[mt][nt][1] * SIM_SCALE);
                    if (i_hi == j_e) g_diag[i_hi] = exp2f(acc[mt][nt][2] * SIM_SCALE);
                    if (i_hi == j_o) g_diag[i_hi] = exp2f(acc[mt][nt][3] * SIM_SCALE);
                }
            }
        }
    } else {
        #pragma unroll
        for (int mt = 0; mt < 4; mt++) {
            int i_lo = i0 + warp_m * 64 + mt * 16 + g;
            int i_hi = i_lo + 8;
            #pragma unroll
            for (int nt = 0; nt < 4; nt++) {
                int j_e = j0 + warp_n * 32 + nt * 8 + 2 * tig;
                int j_o = j_e + 1;
                if (i_lo < N) {
                    if (j_e < N) {
                        float e = exp2f(acc[mt][nt][0] * SIM_SCALE);
                        rp[mt * 2] += e; cp[nt * 2] += e;
                        if (i_lo == j_e) g_diag[i_lo] = e;
                    }
                    if (j_o < N) {
                        float e = exp2f(acc[mt][nt][1] * SIM_SCALE);
                        rp[mt * 2] += e; cp[nt * 2 + 1] += e;
                        if (i_lo == j_o) g_diag[i_lo] = e;
                    }
                }
                if (i_hi < N) {
                    if (j_e < N) {
                        float e = exp2f(acc[mt][nt][2] * SIM_SCALE);
                        rp[mt * 2 + 1] += e; cp[nt * 2] += e;
                        if (i_hi == j_e) g_diag[i_hi] = e;
                    }
                    if (j_o < N) {
                        float e = exp2f(acc[mt][nt][3] * SIM_SCALE);
                        rp[mt * 2 + 1] += e; cp[nt * 2 + 1] += e;
                        if (i_hi == j_o) g_diag[i_hi] = e;
                    }
                }
            }
        }
    }

    #pragma unroll
    for (int r = 0; r < 8; r++) {
        float v = rp[r];
        v += __shfl_xor_sync(0xffffffffu, v, 1);
        v += __shfl_xor_sync(0xffffffffu, v, 2);
        if (tig == 0) {
            int mt = r >> 1, h = r & 1;
            atomicAdd(&sRow[warp_m * 64 + mt * 16 + h * 8 + g], v);
        }
    }
    #pragma unroll
    for (int c = 0; c < 8; c++) {
        float v = cp[c];
        v += __shfl_xor_sync(0xffffffffu, v, 4);
        v += __shfl_xor_sync(0xffffffffu, v, 8);
        v += __shfl_xor_sync(0xffffffffu, v, 16);
        if (g == 0) {
            int nt = c >> 1, par = c & 1;
            atomicAdd(&sCol[warp_n * 32 + nt * 8 + 2 * tig + par], v);
        }
    }
    __syncthreads();

    if (t < TILE) {
        int i = i0 + t;
        if (i < N) atomicAdd(&g_rowsum[i], sRow[t]);
        int j = j0 + t;
        if (j < N) atomicAdd(&g_colsum[j], sCol[t]);
    }
}

// ---------------- 5: motif loss: warp = 2 motifs (16 lanes each, float4) ------
__global__ void motif_kernel(const int* __restrict__ motif,
                             const int* __restrict__ neg_uv,
                             const float* __restrict__ b1,
                             const float* __restrict__ W2,
                             const float* __restrict__ b2,
                             int N, int M) {
    __shared__ double sdm[8];
    const int t = threadIdx.x;
    const int lane = t & 31;
    const int wib = t >> 5;
    const int gw = (blockIdx.x * blockDim.x + t) >> 5;
    const int sl = lane & 15;
    const int half = lane >> 4;
    double local = 0.0;

    int m = gw * 2 + half;
    bool valid = (m < M);
    if (gw * 2 < M) {
        int mc = valid ? m : (M - 1);
        int u0 = motif[mc], v0 = motif[M + mc], w0 = motif[2 * M + mc];
        int u1 = neg_uv[mc], v1 = neg_uv[M + mc];
        float4 b1v = ((const float4*)b1)[sl];
        float4 w2v = ((const float4*)W2)[sl];
        float bb2 = b2[0];

        #pragma unroll
        for (int p = 0; p < 4; p++) {
            const float* base = g_H + (size_t)p * N * 192;
            float4 hw = *(const float4*)(base + (size_t)w0 * 192 + 128 + 4 * sl);
            #pragma unroll
            for (int s = 0; s < 2; s++) {
                int u = s ? u1 : u0;
                int v = s ? v1 : v0;
                float4 hu = *(const float4*)(base + (size_t)u * 192 + 4 * sl);
                float4 hv = *(const float4*)(base + (size_t)v * 192 + 64 + 4 * sl);
                float h0 = hu.x + hv.x + hw.x + b1v.x;
                float h1 = hu.y + hv.y + hw.y + b1v.y;
                float h2 = hu.z + hv.z + hw.z + b1v.z;
                float h3 = hu.w + hv.w + hw.w + b1v.w;
                float acc = fmaxf(h0, 0.f) * w2v.x + fmaxf(h1, 0.f) * w2v.y
                          + fmaxf(h2, 0.f) * w2v.z + fmaxf(h3, 0.f) * w2v.w;
                acc += __shfl_xor_sync(0xffffffffu, acc, 1);
                acc += __shfl_xor_sync(0xffffffffu, acc, 2);
                acc += __shfl_xor_sync(0xffffffffu, acc, 4);
                acc += __shfl_xor_sync(0xffffffffu, acc, 8);
                if (sl == 0 && valid) {
                    float logit = acc + bb2;
                    float z = s ? -logit : logit;
                    local += (double)(fminf(z, 0.f) - log1pf(expf(-fabsf(z))));
                }
            }
        }
    }
    local += __shfl_xor_sync(0xffffffffu, local, 16);
    if (lane == 0) sdm[wib] = local;
    __syncthreads();
    if (t == 0) {
        double sum = 0.0;
        #pragma unroll
        for (int i = 0; i < 8; i++) sum += sdm[i];
        atomicAdd(&g_macc, sum);
    }
}

// ---------------- 6: contrastive-loss partial sums ----------------------------
__global__ void cl_partial_kernel(int N) {
    __shared__ double sd[256];
    int t = threadIdx.x;
    int j = blockIdx.x * 256 + t;
    double dl = 0.0;
    if (j < N) {
        float pos = g_diag[j];
        float lp = logf(pos);
        dl = (double)(2.f * lp - logf(g_colsum[j] - pos) - logf(g_rowsum[j] - pos));
    }
    sd[t] = dl;
    __syncthreads();
    #pragma unroll
    for (int s = 128; s > 0; s >>= 1) {
        if (t < s) sd[t] += sd[t + s];
        __syncthreads();
    }
    if (t == 0) atomicAdd(&g_clacc, sd[0]);
}

// ---------------- 7: combine -> scalar -----------------------------------------
__global__ void combine_kernel(float* __restrict__ out, int N, int M) {
    out[0] = (float)(-0.5 * g_clacc / (double)N - g_macc / (double)M);
}

// ---------------- launch: DAG with stream fork (graph-capturable) --------------
static cudaStream_t g_s2 = nullptr;
static cudaEvent_t g_evFork = nullptr;
static cudaEvent_t g_evJoin = nullptr;

extern "C" void kernel_launch(void* const* d_in, const int* in_sizes, int n_in,
                              void* d_out, int out_size) {
    const float* x         = (const float*)d_in[0];
    const float* feats     = (const float*)d_in[1];
    const float* feat_free = (const float*)d_in[2];
    const float* ks        = (const float*)d_in[3];
    const float* Ws        = (const float*)d_in[4];
    const float* bias      = (const float*)d_in[5];
    const float* W_free    = (const float*)d_in[6];
    const float* b_free    = (const float*)d_in[7];
    const float* W1        = (const float*)d_in[8];
    const float* b1        = (const float*)d_in[9];
    const float* W2        = (const float*)d_in[10];
    const float* b2        = (const float*)d_in[11];
    const int*   motif     = (const int*)d_in[12];
    const int*   neg_uv    = (const int*)d_in[13];
    float* out = (float*)d_out;

    int N = in_sizes[0] / EMB;        // 10000
    int M = in_sizes[12] / 3;         // 50000

    // lazy one-time setup (first call is the uncaptured correctness run)
    if (g_s2 == nullptr) {
        cudaStreamCreateWithFlags(&g_s2, cudaStreamNonBlocking);
        cudaEventCreateWithFlags(&g_evFork, cudaEventDisableTiming);
        cudaEventCreateWithFlags(&g_evJoin, cudaEventDisableTiming);
        cudaFuncSetAttribute(sim_hmma_kernel,
                             cudaFuncAttributeMaxDynamicSharedMemorySize, SIM_SMEM);
    }

    // 1: normalize riemannian features + x (zeros accumulators)     [stream 0]
    norm_all_kernel<<<(4 * N * 32 + 255) / 256, 256>>>(feats, ks, x, N);

    // fork: branch B (H -> motif) depends only on norm_all
    cudaEventRecord(g_evFork, 0);
    cudaStreamWaitEvent(g_s2, g_evFork, 0);

    // branch B [stream s2]: H -> motif  (issued first so its blocks claim
    // residual capacity during branch A's pre-sim window)
    build_H_kernel<<<(4 * N + BH_ROWS - 1) / BH_ROWS, 256, 0, g_s2>>>(feat_free, W1, N);
    {
        int warps = (M + 1) / 2;
        motif_kernel<<<(warps * 32 + 255) / 256, 256, 0, g_s2>>>(
            motif, neg_uv, b1, W2, b2, N, M);
    }
    cudaEventRecord(g_evJoin, g_s2);

    // branch A [stream 0]: x2 -> sim
    build_x2_kernel<<<(N + X2_ROWS - 1) / X2_ROWS, 256>>>(
        feat_free, ks, Ws, bias, W_free, b_free, N);
    {
        dim3 grid((N + TILE - 1) / TILE, (N + TILE - 1) / TILE);
        sim_hmma_kernel<<<grid, 256, SIM_SMEM>>>(N);
    }

    // join, then finalize on stream 0
    cudaStreamWaitEvent(0, g_evJoin, 0);
    cl_partial_kernel<<<(N + 255) / 256, 256>>>(N);
    combine_kernel<<<1, 1>>>(out, N, M);
}

// round 17
// speedup vs baseline: 1.0162x; 1.0162x over previous
#include <cuda_runtime.h>
#include <cuda_bf16.h>
#include <cuda_fp8.h>
#include <math.h>
#include <stdint.h>

// Problem-instance maxima (N=10000, M=50000, fixed shapes per reference)
#define NMAX 10016
#define D_IN 32
#define DOUT 64
#define EMB 256
#define EPS 1e-5f
// log2(e)/TEMP,  TEMP = 0.2
#define SIM_SCALE 7.2134752044448170f

// ---------------- scratch (static device globals; no allocation) -------------
__device__ float g_prod[3 * NMAX * D_IN];             // normalized riemannian feats
__device__ uint8_t g_xa[NMAX * EMB];                  // row-normalized x   (fp8 e4m3)
__device__ uint8_t g_xb[NMAX * EMB];                  // row-normalized x2  (fp8 e4m3)
__device__ float g_H[4 * NMAX * 192];                 // MLP layer-1 partials
__device__ float g_rowsum[NMAX];
__device__ float g_colsum[NMAX];
__device__ float g_diag[NMAX];
__device__ double g_macc;                             // motif log-sigmoid sum
__device__ double g_clacc;                            // contrastive log-ratio sum

__device__ __forceinline__ uint32_t smem_u32(const void* p) {
    uint32_t a;
    asm("{ .reg .u64 t; cvta.to.shared.u64 t, %1; cvt.u32.u64 %0, t; }" : "=r"(a) : "l"(p));
    return a;
}
__device__ __forceinline__ void cp_async16(uint32_t dst, const void* src, bool pred) {
    int sz = pred ? 16 : 0;
    asm volatile("cp.async.cg.shared.global [%0], [%1], 16, %2;"
                 :: "r"(dst), "l"(src), "r"(sz) : "memory");
}
#define CP_COMMIT() asm volatile("cp.async.commit_group;" ::: "memory")
#define CP_WAIT(n)  asm volatile("cp.async.wait_group %0;" :: "n"(n) : "memory")

__device__ __forceinline__ uint32_t to_fp8(float v) {
    __nv_fp8_e4m3 f(v);
    return (uint32_t)*reinterpret_cast<uint8_t*>(&f);
}

// ---------------- 1: normalize feats AND x (merged, + zero accumulators) ------
__global__ void norm_all_kernel(const float* __restrict__ feats,
                                const float* __restrict__ ks,
                                const float* __restrict__ x, int N) {
    int tid = blockIdx.x * blockDim.x + threadIdx.x;
    if (tid < N) { g_rowsum[tid] = 0.f; g_colsum[tid] = 0.f; }
    if (tid == 0) { g_macc = 0.0; g_clacc = 0.0; }
    int gw = tid >> 5;
    int lane = tid & 31;
    if (gw < 3 * N) {
        float v = feats[(size_t)gw * D_IN + lane];
        float sq = v * v;
        #pragma unroll
        for (int off = 16; off; off >>= 1) sq += __shfl_xor_sync(0xffffffffu, sq, off);
        float k = ks[gw / N];
        float scale = 0.45f / (sqrtf(sq) * sqrtf(fabsf(k)));
        g_prod[(size_t)gw * D_IN + lane] = v * scale;
    } else if (gw < 4 * N) {
        int row = gw - 3 * N;
        const float4* rp = (const float4*)(x + (size_t)row * EMB);
        float4 v0 = rp[lane * 2];
        float4 v1 = rp[lane * 2 + 1];
        float sq = v0.x * v0.x + v0.y * v0.y + v0.z * v0.z + v0.w * v0.w
                 + v1.x * v1.x + v1.y * v1.y + v1.z * v1.z + v1.w * v1.w;
        #pragma unroll
        for (int off = 16; off; off >>= 1) sq += __shfl_xor_sync(0xffffffffu, sq, off);
        float inv = rsqrtf(sq);
        uint2 o;
        o.x = to_fp8(v0.x * inv) | (to_fp8(v0.y * inv) << 8)
            | (to_fp8(v0.z * inv) << 16) | (to_fp8(v0.w * inv) << 24);
        o.y = to_fp8(v1.x * inv) | (to_fp8(v1.y * inv) << 8)
            | (to_fp8(v1.z * inv) << 16) | (to_fp8(v1.w * inv) << 24);
        *(uint2*)(g_xa + (size_t)row * EMB + lane * 8) = o;
    }
}

// ---------------- 2: build x2 (random mapping), normalize, -> fp8 -------------
#define X2_ROWS 8
__global__ __launch_bounds__(256) void build_x2_kernel(
        const float* __restrict__ feat_free,
        const float* __restrict__ ks,
        const float* __restrict__ Ws,
        const float* __restrict__ bias,
        const float* __restrict__ W_free,
        const float* __restrict__ b_free,
        int N) {
    __shared__ float ws[3 * 32 * 65];     // [f][c][col], c-stride 65
    __shared__ float wf[32 * 65];         // [c][col]
    __shared__ float xi[X2_ROWS][128];
    __shared__ float red[X2_ROWS][256];
    const int n0 = blockIdx.x * X2_ROWS;
    const int t = threadIdx.x;

    #pragma unroll
    for (int k = 0; k < 6; k++) {
        int idx4 = t + k * 256;
        float4 v = ((const float4*)Ws)[idx4];
        int row = idx4 >> 3;
        int c0 = (idx4 & 7) * 4;
        int f = row >> 6, col = row & 63;
        float* dst = ws + f * (32 * 65) + col;
        dst[(c0 + 0) * 65] = v.x; dst[(c0 + 1) * 65] = v.y;
        dst[(c0 + 2) * 65] = v.z; dst[(c0 + 3) * 65] = v.w;
    }
    #pragma unroll
    for (int k = 0; k < 2; k++) {
        int idx4 = t + k * 256;
        float4 v = ((const float4*)W_free)[idx4];
        int col = idx4 >> 3;
        int c0 = (idx4 & 7) * 4;
        float* dst = wf + col;
        dst[(c0 + 0) * 65] = v.x; dst[(c0 + 1) * 65] = v.y;
        dst[(c0 + 2) * 65] = v.z; dst[(c0 + 3) * 65] = v.w;
    }
    #pragma unroll
    for (int rr = 0; rr < 4; rr++) {
        int idx = t + rr * 256;
        int r = idx >> 7;
        int c = idx & 127;
        int n = n0 + r;
        float v;
        if (n < N) {
            v = (c < 96) ? g_prod[((c >> 5) * N + n) * D_IN + (c & 31)]
                         : feat_free[n * D_IN + (c - 96)];
        } else v = 1.f;
        xi[r][c] = v;
    }
    __syncthreads();

    const int f = t >> 6;
    const int col = t & 63;
    const float kf = (f < 3) ? ks[f] : 0.f;
    const float bv = (f < 3) ? bias[f * DOUT + col] : b_free[col];

    float z[X2_ROWS];
    #pragma unroll
    for (int r = 0; r < X2_ROWS; r++) {
        float zv;
        if (f < 3) {
            const float* xv = xi[r] + f * D_IN;
            const float* wv = ws + f * (32 * 65) + col;
            float nsq = 0.f, dot = 0.f;
            #pragma unroll
            for (int c = 0; c < D_IN; c++) {
                float xc = xv[c];
                nsq += xc * xc;
                dot += xc * wv[c * 65];
            }
            float div = nsq - 2.f * dot + 1.f;
            float num = 1.f + kf * nsq;
            float dist = logf(num / (div + EPS));
            zv = expf(15.5f * dist) * cosf(dist + bv);
        } else {
            const float* xv = xi[r] + 3 * D_IN;
            const float* wv = wf + col;
            float dot = 0.f;
            #pragma unroll
            for (int c = 0; c < D_IN; c++) dot += xv[c] * wv[c * 65];
            zv = expf(15.5f * dot) * cosf(dot + bv);
        }
        z[r] = zv;
        red[r][t] = zv * zv;
    }
    __syncthreads();
    #pragma unroll
    for (int s = 128; s > 0; s >>= 1) {
        if (t < s) {
            #pragma unroll
            for (int r = 0; r < X2_ROWS; r++) red[r][t] += red[r][t + s];
        }
        __syncthreads();
    }
    #pragma unroll
    for (int r = 0; r < X2_ROWS; r++) {
        int n = n0 + r;
        if (n < N) {
            float inv = rsqrtf(red[r][0]);
            g_xb[(size_t)n * EMB + t] = (uint8_t)to_fp8(z[r] * inv);
        }
    }
}

// ---------------- 3: H = product_p @ W1 (2 rows x 4 cols per thread) ----------
#define BH_ROWS 32
__global__ __launch_bounds__(256) void build_H_kernel(
        const float* __restrict__ feat_free,
        const float* __restrict__ W1, int N) {
    __shared__ float w1s[96 * 64];        // 24 KB
    __shared__ float rows[BH_ROWS][33];   // 4.2 KB, padded
    const int t = threadIdx.x;
    const int q0 = blockIdx.x * BH_ROWS;

    #pragma unroll
    for (int k = 0; k < 6; k++) {
        int i4 = t + k * 256;
        ((float4*)w1s)[i4] = ((const float4*)W1)[i4];
    }
    #pragma unroll
    for (int k = 0; k < 4; k++) {
        int idx = t + k * 256;
        int r = idx >> 5, c = idx & 31;
        int q = q0 + r;
        float v = 0.f;
        if (q < 4 * N) {
            int p = q / N, n = q % N;
            v = (p < 3) ? g_prod[((size_t)p * N + n) * D_IN + c]
                        : feat_free[(size_t)n * D_IN + c];
        }
        rows[r][c] = v;
    }
    __syncthreads();

    const int jj = (t & 15) * 4;          // 16 col groups
    const int r0 = (t >> 4) * 2;          // 16 row groups x 2 rows
    #pragma unroll
    for (int part = 0; part < 3; part++) {
        float4 a0 = make_float4(0.f, 0.f, 0.f, 0.f);
        float4 a1 = make_float4(0.f, 0.f, 0.f, 0.f);
        #pragma unroll
        for (int c = 0; c < 32; c++) {
            float4 w = *(const float4*)&w1s[(part * 32 + c) * 64 + jj];
            float r0v = rows[r0][c];
            float r1v = rows[r0 + 1][c];
            a0.x += r0v * w.x; a0.y += r0v * w.y; a0.z += r0v * w.z; a0.w += r0v * w.w;
            a1.x += r1v * w.x; a1.y += r1v * w.y; a1.z += r1v * w.z; a1.w += r1v * w.w;
        }
        int q = q0 + r0;
        if (q < 4 * N)
            *(float4*)(g_H + (size_t)q * 192 + part * 64 + jj) = a0;
        if (q + 1 < 4 * N)
            *(float4*)(g_H + (size_t)(q + 1) * 192 + part * 64 + jj) = a1;
    }
}

// ---------------- 4: sim GEMM: fp8 e4m3 mma.sync m16n8k32 ----------------------
#define TILE 128
#define BKB 128               // bytes of K per stage (= 128 fp8 elems)
#define RSB 144               // smem row stride in bytes (128 data + 16 pad)
#define MAT_BYTES (TILE * RSB)             // 18432
#define STAGE_BYTES (2 * MAT_BYTES)        // 36864
#define SIM_SMEM (2 * STAGE_BYTES)         // 73728

__global__ __launch_bounds__(256, 2) void sim_hmma_kernel(int N) {
    extern __shared__ char dynsm[];
    __shared__ float sRow[TILE];
    __shared__ float sCol[TILE];

    const uint32_t sbase = smem_u32(dynsm);
    const int t = threadIdx.x;
    const int lane = t & 31;
    const int wid = t >> 5;
    const int warp_m = wid & 1;
    const int warp_n = wid >> 1;
    const int g = lane >> 2;
    const int tig = lane & 3;
    const int i0 = blockIdx.y * TILE;
    const int j0 = blockIdx.x * TILE;

    const uint8_t* GA = g_xa;
    const uint8_t* GB = g_xb;

    if (t < TILE) { sRow[t] = 0.f; sCol[t] = 0.f; }

    {
        #pragma unroll
        for (int it = 0; it < 4; it++) {
            int id = t + it * 256;
            int row = id >> 3, ch = id & 7;
            cp_async16(sbase + row * RSB + ch * 16,
                       GA + (size_t)(i0 + row) * EMB + ch * 16, i0 + row < N);
        }
        #pragma unroll
        for (int it = 0; it < 4; it++) {
            int id = t + it * 256;
            int row = id >> 3, ch = id & 7;
            cp_async16(sbase + MAT_BYTES + row * RSB + ch * 16,
                       GB + (size_t)(j0 + row) * EMB + ch * 16, j0 + row < N);
        }
        CP_COMMIT();
    }

    float acc[4][4][4];
    #pragma unroll
    for (int mt = 0; mt < 4; mt++)
        #pragma unroll
        for (int nt = 0; nt < 4; nt++)
            #pragma unroll
            for (int c = 0; c < 4; c++) acc[mt][nt][c] = 0.f;

    const int aRow = lane & 15;
    const int aColB = (lane >> 4) * 16;
    const int bRow = (lane & 7) + ((lane >> 4) << 3);
    const int bColB = ((lane >> 3) & 1) * 16;

    #pragma unroll
    for (int s = 0; s < EMB / BKB; s++) {
        CP_WAIT(0);
        __syncthreads();

        if (s + 1 < EMB / BKB) {
            uint32_t dst = sbase + ((s + 1) & 1) * STAGE_BYTES;
            const int koff = (s + 1) * BKB;
            #pragma unroll
            for (int it = 0; it < 4; it++) {
                int id = t + it * 256;
                int row = id >> 3, ch = id & 7;
                cp_async16(dst + row * RSB + ch * 16,
                           GA + (size_t)(i0 + row) * EMB + koff + ch * 16, i0 + row < N);
            }
            #pragma unroll
            for (int it = 0; it < 4; it++) {
                int id = t + it * 256;
                int row = id >> 3, ch = id & 7;
                cp_async16(dst + MAT_BYTES + row * RSB + ch * 16,
                           GB + (size_t)(j0 + row) * EMB + koff + ch * 16, j0 + row < N);
            }
            CP_COMMIT();
        }

        const uint32_t aB = sbase + (s & 1) * STAGE_BYTES;
        const uint32_t bB = aB + MAT_BYTES;

        #pragma unroll
        for (int kk = 0; kk < BKB / 32; kk++) {
            const int k0b = kk * 32;
            uint32_t a[4][4];
            #pragma unroll
            for (int mt = 0; mt < 4; mt++) {
                uint32_t addr = aB + (warp_m * 64 + mt * 16 + aRow) * RSB + k0b + aColB;
                asm volatile("ldmatrix.sync.aligned.m8n8.x4.shared.b16 {%0,%1,%2,%3}, [%4];"
                             : "=r"(a[mt][0]), "=r"(a[mt][1]), "=r"(a[mt][2]), "=r"(a[mt][3])
                             : "r"(addr));
            }
            uint32_t b[4][2];
            #pragma unroll
            for (int bq = 0; bq < 2; bq++) {
                uint32_t addr = bB + (warp_n * 32 + bq * 16 + bRow) * RSB + k0b + bColB;
                uint32_t r0, r1, r2, r3;
                asm volatile("ldmatrix.sync.aligned.m8n8.x4.shared.b16 {%0,%1,%2,%3}, [%4];"
                             : "=r"(r0), "=r"(r1), "=r"(r2), "=r"(r3)
                             : "r"(addr));
                b[bq * 2][0] = r0;     b[bq * 2][1] = r1;
                b[bq * 2 + 1][0] = r2; b[bq * 2 + 1][1] = r3;
            }
            #pragma unroll
            for (int mt = 0; mt < 4; mt++)
                #pragma unroll
                for (int nt = 0; nt < 4; nt++) {
                    asm volatile(
                        "mma.sync.aligned.m16n8k32.row.col.f32.e4m3.e4m3.f32 "
                        "{%0,%1,%2,%3}, {%4,%5,%6,%7}, {%8,%9}, {%0,%1,%2,%3};"
                        : "+f"(acc[mt][nt][0]), "+f"(acc[mt][nt][1]),
                          "+f"(acc[mt][nt][2]), "+f"(acc[mt][nt][3])
                        : "r"(a[mt][0]), "r"(a[mt][1]), "r"(a[mt][2]), "r"(a[mt][3]),
                          "r"(b[nt][0]), "r"(b[nt][1]));
                }
        }
    }

    const bool full = (i0 + TILE <= N) && (j0 + TILE <= N);
    const bool isdiag = (i0 == j0);

    float rp[8];
    float cp[8];
    #pragma unroll
    for (int r = 0; r < 8; r++) { rp[r] = 0.f; cp[r] = 0.f; }

    if (full) {
        #pragma unroll
        for (int mt = 0; mt < 4; mt++) {
            #pragma unroll
            for (int nt = 0; nt < 4; nt++) {
                float e0 = exp2f(acc[mt][nt][0] * SIM_SCALE);
                float e1 = exp2f(acc[mt][nt][1] * SIM_SCALE);
                float e2 = exp2f(acc[mt][nt][2] * SIM_SCALE);
                float e3 = exp2f(acc[mt][nt][3] * SIM_SCALE);
                rp[mt * 2]     += e0 + e1;
                rp[mt * 2 + 1] += e2 + e3;
                cp[nt * 2]     += e0 + e2;
                cp[nt * 2 + 1] += e1 + e3;
            }
        }
        if (isdiag) {
            #pragma unroll
            for (int mt = 0; mt < 4; mt++) {
                int i_lo = i0 + warp_m * 64 + mt * 16 + g;
                int i_hi = i_lo + 8;
                #pragma unroll
                for (int nt = 0; nt < 4; nt++) {
                    int j_e = j0 + warp_n * 32 + nt * 8 + 2 * tig;
                    int j_o = j_e + 1;
                    if (i_lo == j_e) g_diag[i_lo] = exp2f(acc[mt][nt][0] * SIM_SCALE);
                    if (i_lo == j_o) g_diag[i_lo] = exp2f(acc[mt][nt][1] * SIM_SCALE);
                    if (i_hi == j_e) g_diag[i_hi] = exp2f(acc[mt][nt][2] * SIM_SCALE);
                    if (i_hi == j_o) g_diag[i_hi] = exp2f(acc[mt][nt][3] * SIM_SCALE);
                }
            }
        }
    } else {
        #pragma unroll
        for (int mt = 0; mt < 4; mt++) {
            int i_lo = i0 + warp_m * 64 + mt * 16 + g;
            int i_hi = i_lo + 8;
            #pragma unroll
            for (int nt = 0; nt < 4; nt++) {
                int j_e = j0 + warp_n * 32 + nt * 8 + 2 * tig;
                int j_o = j_e + 1;
                if (i_lo < N) {
                    if (j_e < N) {
                        float e = exp2f(acc[mt][nt][0] * SIM_SCALE);
                        rp[mt * 2] += e; cp[nt * 2] += e;
                        if (i_lo == j_e) g_diag[i_lo] = e;
                    }
                    if (j_o < N) {
                        float e = exp2f(acc[mt][nt][1] * SIM_SCALE);
                        rp[mt * 2] += e; cp[nt * 2 + 1] += e;
                        if (i_lo == j_o) g_diag[i_lo] = e;
                    }
                }
                if (i_hi < N) {
                    if (j_e < N) {
                        float e = exp2f(acc[mt][nt][2] * SIM_SCALE);
                        rp[mt * 2 + 1] += e; cp[nt * 2] += e;
                        if (i_hi == j_e) g_diag[i_hi] = e;
                    }
                    if (j_o < N) {
                        float e = exp2f(acc[mt][nt][3] * SIM_SCALE);
                        rp[mt * 2 + 1] += e; cp[nt * 2 + 1] += e;
                        if (i_hi == j_o) g_diag[i_hi] = e;
                    }
                }
            }
        }
    }

    #pragma unroll
    for (int r = 0; r < 8; r++) {
        float v = rp[r];
        v += __shfl_xor_sync(0xffffffffu, v, 1);
        v += __shfl_xor_sync(0xffffffffu, v, 2);
        if (tig == 0) {
            int mt = r >> 1, h = r & 1;
            atomicAdd(&sRow[warp_m * 64 + mt * 16 + h * 8 + g], v);
        }
    }
    #pragma unroll
    for (int c = 0; c < 8; c++) {
        float v = cp[c];
        v += __shfl_xor_sync(0xffffffffu, v, 4);
        v += __shfl_xor_sync(0xffffffffu, v, 8);
        v += __shfl_xor_sync(0xffffffffu, v, 16);
        if (g == 0) {
            int nt = c >> 1, par = c & 1;
            atomicAdd(&sCol[warp_n * 32 + nt * 8 + 2 * tig + par], v);
        }
    }
    __syncthreads();

    if (t < TILE) {
        int i = i0 + t;
        if (i < N) atomicAdd(&g_rowsum[i], sRow[t]);
        int j = j0 + t;
        if (j < N) atomicAdd(&g_colsum[j], sCol[t]);
    }
}

// ---------------- 5: motif loss: warp = 2 motifs (16 lanes each, float4) ------
__global__ void motif_kernel(const int* __restrict__ motif,
                             const int* __restrict__ neg_uv,
                             const float* __restrict__ b1,
                             const float* __restrict__ W2,
                             const float* __restrict__ b2,
                             int N, int M) {
    __shared__ double sdm[8];
    const int t = threadIdx.x;
    const int lane = t & 31;
    const int wib = t >> 5;
    const int gw = (blockIdx.x * blockDim.x + t) >> 5;
    const int sl = lane & 15;
    const int half = lane >> 4;
    double local = 0.0;

    int m = gw * 2 + half;
    bool valid = (m < M);
    if (gw * 2 < M) {
        int mc = valid ? m : (M - 1);
        int u0 = motif[mc], v0 = motif[M + mc], w0 = motif[2 * M + mc];
        int u1 = neg_uv[mc], v1 = neg_uv[M + mc];
        float4 b1v = ((const float4*)b1)[sl];
        float4 w2v = ((const float4*)W2)[sl];
        float bb2 = b2[0];

        #pragma unroll
        for (int p = 0; p < 4; p++) {
            const float* base = g_H + (size_t)p * N * 192;
            float4 hw = *(const float4*)(base + (size_t)w0 * 192 + 128 + 4 * sl);
            #pragma unroll
            for (int s = 0; s < 2; s++) {
                int u = s ? u1 : u0;
                int v = s ? v1 : v0;
                float4 hu = *(const float4*)(base + (size_t)u * 192 + 4 * sl);
                float4 hv = *(const float4*)(base + (size_t)v * 192 + 64 + 4 * sl);
                float h0 = hu.x + hv.x + hw.x + b1v.x;
                float h1 = hu.y + hv.y + hw.y + b1v.y;
                float h2 = hu.z + hv.z + hw.z + b1v.z;
                float h3 = hu.w + hv.w + hw.w + b1v.w;
                float acc = fmaxf(h0, 0.f) * w2v.x + fmaxf(h1, 0.f) * w2v.y
                          + fmaxf(h2, 0.f) * w2v.z + fmaxf(h3, 0.f) * w2v.w;
                acc += __shfl_xor_sync(0xffffffffu, acc, 1);
                acc += __shfl_xor_sync(0xffffffffu, acc, 2);
                acc += __shfl_xor_sync(0xffffffffu, acc, 4);
                acc += __shfl_xor_sync(0xffffffffu, acc, 8);
                if (sl == 0 && valid) {
                    float logit = acc + bb2;
                    float z = s ? -logit : logit;
                    local += (double)(fminf(z, 0.f) - log1pf(expf(-fabsf(z))));
                }
            }
        }
    }
    local += __shfl_xor_sync(0xffffffffu, local, 16);
    if (lane == 0) sdm[wib] = local;
    __syncthreads();
    if (t == 0) {
        double sum = 0.0;
        #pragma unroll
        for (int i = 0; i < 8; i++) sum += sdm[i];
        atomicAdd(&g_macc, sum);
    }
}

// ---------------- 6: contrastive-loss partial sums ----------------------------
__global__ void cl_partial_kernel(int N) {
    __shared__ double sd[256];
    int t = threadIdx.x;
    int j = blockIdx.x * 256 + t;
    double dl = 0.0;
    if (j < N) {
        float pos = g_diag[j];
        float lp = logf(pos);
        dl = (double)(2.f * lp - logf(g_colsum[j] - pos) - logf(g_rowsum[j] - pos));
    }
    sd[t] = dl;
    __syncthreads();
    #pragma unroll
    for (int s = 128; s > 0; s >>= 1) {
        if (t < s) sd[t] += sd[t + s];
        __syncthreads();
    }
    if (t == 0) atomicAdd(&g_clacc, sd[0]);
}

// ---------------- 7: combine -> scalar -----------------------------------------
__global__ void combine_kernel(float* __restrict__ out, int N, int M) {
    out[0] = (float)(-0.5 * g_clacc / (double)N - g_macc / (double)M);
}

// ---------------- launch: DAG with prioritized stream fork ---------------------
static cudaStream_t g_sHi = nullptr;    // branch A: x2 -> sim (high priority)
static cudaStream_t g_sLo = nullptr;    // branch B: H -> motif (low priority)
static cudaEvent_t g_evFork = nullptr;
static cudaEvent_t g_evA = nullptr;
static cudaEvent_t g_evB = nullptr;

extern "C" void kernel_launch(void* const* d_in, const int* in_sizes, int n_in,
                              void* d_out, int out_size) {
    const float* x         = (const float*)d_in[0];
    const float* feats     = (const float*)d_in[1];
    const float* feat_free = (const float*)d_in[2];
    const float* ks        = (const float*)d_in[3];
    const float* Ws        = (const float*)d_in[4];
    const float* bias      = (const float*)d_in[5];
    const float* W_free    = (const float*)d_in[6];
    const float* b_free    = (const float*)d_in[7];
    const float* W1        = (const float*)d_in[8];
    const float* b1        = (const float*)d_in[9];
    const float* W2        = (const float*)d_in[10];
    const float* b2        = (const float*)d_in[11];
    const int*   motif     = (const int*)d_in[12];
    const int*   neg_uv    = (const int*)d_in[13];
    float* out = (float*)d_out;

    int N = in_sizes[0] / EMB;        // 10000
    int M = in_sizes[12] / 3;         // 50000

    // lazy one-time setup (first call is the uncaptured correctness run)
    if (g_sHi == nullptr) {
        int loPrio, hiPrio;   // loPrio = least (numerically largest), hiPrio = greatest
        cudaDeviceGetStreamPriorityRange(&loPrio, &hiPrio);
        cudaStreamCreateWithPriority(&g_sHi, cudaStreamNonBlocking, hiPrio);
        cudaStreamCreateWithPriority(&g_sLo, cudaStreamNonBlocking, loPrio);
        cudaEventCreateWithFlags(&g_evFork, cudaEventDisableTiming);
        cudaEventCreateWithFlags(&g_evA, cudaEventDisableTiming);
        cudaEventCreateWithFlags(&g_evB, cudaEventDisableTiming);
        cudaFuncSetAttribute(sim_hmma_kernel,
                             cudaFuncAttributeMaxDynamicSharedMemorySize, SIM_SMEM);
    }

    // 1: normalize riemannian features + x (zeros accumulators)     [stream 0]
    norm_all_kernel<<<(4 * N * 32 + 255) / 256, 256>>>(feats, ks, x, N);
    cudaEventRecord(g_evFork, 0);
    cudaStreamWaitEvent(g_sHi, g_evFork, 0);
    cudaStreamWaitEvent(g_sLo, g_evFork, 0);

    // branch B [low priority]: H -> motif (backfills around branch A)
    build_H_kernel<<<(4 * N + BH_ROWS - 1) / BH_ROWS, 256, 0, g_sLo>>>(feat_free, W1, N);
    {
        int warps = (M + 1) / 2;
        motif_kernel<<<(warps * 32 + 255) / 256, 256, 0, g_sLo>>>(
            motif, neg_uv, b1, W2, b2, N, M);
    }
    cudaEventRecord(g_evB, g_sLo);

    // branch A [high priority]: x2 -> sim -> cl_partial (cl needs only sim outputs)
    build_x2_kernel<<<(N + X2_ROWS - 1) / X2_ROWS, 256, 0, g_sHi>>>(
        feat_free, ks, Ws, bias, W_free, b_free, N);
    {
        dim3 grid((N + TILE - 1) / TILE, (N + TILE - 1) / TILE);
        sim_hmma_kernel<<<grid, 256, SIM_SMEM, g_sHi>>>(N);
    }
    cl_partial_kernel<<<(N + 255) / 256, 256, 0, g_sHi>>>(N);
    cudaEventRecord(g_evA, g_sHi);

    // join on stream 0: combine needs both branches
    cudaStreamWaitEvent(0, g_evA, 0);
    cudaStreamWaitEvent(0, g_evB, 0);
    combine_kernel<<<1, 1>>>(out, N, M);
}